// round 1
// baseline (speedup 1.0000x reference)
#include <cuda_runtime.h>
#include <cuda_bf16.h>
#include <math.h>

// Problem constants
#define NB 64          // graphs
#define LG 1024        // nodes per graph
#define NN (NB*LG)     // 65536 total nodes
#define KK 16          // kNN
#define INF_ 128       // in features
#define OUTF 128       // out features
#define SS 4           // space dims
#define FLR 64         // propagated dims
#define FEAT 256       // IN + 2*FLR

// Scratch (device globals: allocation is forbidden)
__device__ float g_s[NN * SS];          // 1 MB
__device__ float g_h[NN * FLR];         // 16.8 MB
__device__ float g_agg[NN * 2 * FLR];   // 33.6 MB (mean | max)

// ---------------------------------------------------------------------------
// Kernel 1: s = x@W_s + b_s  (N,4)   and   h = x@W_h + b_h  (N,64)
// Warp-per-row; W_s/W_h resident in shared.
// ---------------------------------------------------------------------------
__global__ __launch_bounds__(256) void k1_embed(
    const float* __restrict__ x,
    const float* __restrict__ Ws, const float* __restrict__ bs,
    const float* __restrict__ Wh, const float* __restrict__ bh)
{
    __shared__ float sWh[INF_ * FLR];   // 32 KB
    __shared__ float sWs[INF_ * SS];    // 2 KB
    __shared__ float sbh[FLR];
    __shared__ float sbs[SS];
    __shared__ float xbuf[8][INF_];     // per-warp x row

    int tid = threadIdx.x;
    for (int i = tid; i < INF_ * FLR; i += 256) sWh[i] = Wh[i];
    for (int i = tid; i < INF_ * SS;  i += 256) sWs[i] = Ws[i];
    if (tid < FLR) sbh[tid] = bh[tid];
    if (tid < SS)  sbs[tid] = bs[tid];
    __syncthreads();

    int warp = tid >> 5, lane = tid & 31;
    int gw = blockIdx.x * 8 + warp;
    int nw = gridDim.x * 8;
    int sl = lane & 3;

    for (int row = gw; row < NN; row += nw) {
        const float4* xr = (const float4*)(x + (size_t)row * INF_);
        ((float4*)xbuf[warp])[lane] = xr[lane];   // 32*4 = 128 floats
        __syncwarp();

        float a0 = 0.f, a1 = 0.f, as = 0.f;
        #pragma unroll 8
        for (int i = 0; i < INF_; i++) {
            float xv = xbuf[warp][i];
            a0 = fmaf(xv, sWh[i * FLR + lane],      a0);
            a1 = fmaf(xv, sWh[i * FLR + 32 + lane], a1);
            as = fmaf(xv, sWs[i * SS + sl],         as);
        }
        g_h[(size_t)row * FLR + lane]      = a0 + sbh[lane];
        g_h[(size_t)row * FLR + 32 + lane] = a1 + sbh[32 + lane];
        if (lane < SS) g_s[(size_t)row * SS + lane] = as + sbs[lane];
        __syncwarp();
    }
}

// ---------------------------------------------------------------------------
// Kernel 2: per-graph pairwise d2, top-16 (smallest d2, ties -> lower index,
// identical to stable top_k), fused gather + exp weight + mean/max aggregate.
// 4 warps per block = 4 nodes per block; s-tile for the graph in shared.
// ---------------------------------------------------------------------------
__global__ __launch_bounds__(128) void k2_knn_agg()
{
    __shared__ float4 s_sh[LG];         // 16 KB
    __shared__ float  sq_sh[LG];        // 4 KB
    __shared__ float  d2[4][LG];        // 16 KB
    __shared__ int    sel_idx[4][KK];
    __shared__ float  sel_w[4][KK];

    int g    = blockIdx.x >> 8;     // /256 (blocks per graph = 1024/4)
    int nb   = blockIdx.x & 255;
    int tid  = threadIdx.x;
    int warp = tid >> 5, lane = tid & 31;
    int gbase = g * LG;

    // Load s tile + squared norms
    const float4* sg = (const float4*)(g_s + (size_t)gbase * SS);
    for (int i = tid; i < LG; i += 128) {
        float4 v = sg[i];
        s_sh[i] = v;
        sq_sh[i] = v.x*v.x + v.y*v.y + v.z*v.z + v.w*v.w;
    }
    __syncthreads();

    int li = nb * 4 + warp;             // local node this warp owns
    float4 si = s_sh[li];
    float sqi = sq_sh[li];
    float* drow = d2[warp];

    // d2 row (exact reference formula: sq_i + sq_j - 2*dot, clamped at 0)
    #pragma unroll
    for (int c = 0; c < 32; c++) {
        int j = c * 32 + lane;
        float4 sj = s_sh[j];
        float dot = si.x*sj.x + si.y*sj.y + si.z*sj.z + si.w*sj.w;
        float v = sqi + sq_sh[j] - 2.f * dot;
        drow[j] = fmaxf(v, 0.f);
    }
    __syncwarp();

    // 16 argmin passes (ties -> smallest index)
    for (int t = 0; t < KK; t++) {
        float bv = 3.4e38f;
        int   bi = 0x7fffffff;
        #pragma unroll
        for (int c = 0; c < 32; c++) {
            int j = c * 32 + lane;
            float v = drow[j];
            if (v < bv) { bv = v; bi = j; }   // ascending j => first/lowest idx kept
        }
        #pragma unroll
        for (int off = 16; off; off >>= 1) {
            float ov = __shfl_down_sync(0xffffffffu, bv, off);
            int   oi = __shfl_down_sync(0xffffffffu, bi, off);
            if (ov < bv || (ov == bv && oi < bi)) { bv = ov; bi = oi; }
        }
        bi = __shfl_sync(0xffffffffu, bi, 0);
        bv = __shfl_sync(0xffffffffu, bv, 0);
        if ((bi & 31) == lane) drow[bi] = 3.4e38f;   // remove winner
        if (lane == 0) { sel_idx[warp][t] = bi; sel_w[warp][t] = expf(-10.f * bv); }
        __syncwarp();
    }

    // Gather + aggregate (lane handles dims lane and lane+32)
    float m0 = 0.f, m1 = 0.f, x0 = -3.4e38f, x1 = -3.4e38f;
    #pragma unroll
    for (int t = 0; t < KK; t++) {
        int   j  = sel_idx[warp][t];
        float wt = sel_w[warp][t];
        const float* hp = g_h + (size_t)(gbase + j) * FLR;
        float v0 = hp[lane]      * wt;
        float v1 = hp[lane + 32] * wt;
        m0 += v0; m1 += v1;
        x0 = fmaxf(x0, v0); x1 = fmaxf(x1, v1);
    }
    float* ap = g_agg + (size_t)(gbase + li) * (2 * FLR);
    ap[lane]      = m0 * (1.f / 16.f);
    ap[lane + 32] = m1 * (1.f / 16.f);
    ap[64 + lane] = x0;
    ap[96 + lane] = x1;
}

// ---------------------------------------------------------------------------
// Kernel 3: out = relu([x | agg] @ W_out + b_out).  W_out (128 KB) in shared.
// Each warp: 2 rows, 4 outputs per lane -> 8 FMA per (LDS.128 + 2 broadcasts).
// ---------------------------------------------------------------------------
__global__ __launch_bounds__(512) void k3_out(
    const float* __restrict__ x,
    const float* __restrict__ Wout, const float* __restrict__ bout,
    float* __restrict__ out)
{
    extern __shared__ float sm[];
    float* Wsh = sm;                        // 256*128 floats
    float* fb  = sm + FEAT * OUTF;          // 16 warps * 512 floats

    int tid = threadIdx.x;
    for (int i = tid; i < FEAT * OUTF; i += 512) Wsh[i] = Wout[i];
    __syncthreads();

    int warp = tid >> 5, lane = tid & 31;
    float* fw = fb + warp * 512;
    float4* f4 = (float4*)fw;
    float4 bo = ((const float4*)bout)[lane];
    const float4* W4 = (const float4*)Wsh;

    int gw = blockIdx.x * 16 + warp;
    int nw = gridDim.x * 16;

    for (int p = gw; p < NN / 2; p += nw) {
        int r0 = p * 2;
        #pragma unroll
        for (int row = 0; row < 2; row++) {
            const float4* xr = (const float4*)(x     + (size_t)(r0 + row) * INF_);
            const float4* ar = (const float4*)(g_agg + (size_t)(r0 + row) * (2 * FLR));
            f4[row * 64 + lane]      = xr[lane];   // feats[0:128]  = x row
            f4[row * 64 + 32 + lane] = ar[lane];   // feats[128:256]= [mean|max]
        }
        __syncwarp();

        float4 a0 = make_float4(0.f, 0.f, 0.f, 0.f);
        float4 a1 = make_float4(0.f, 0.f, 0.f, 0.f);
        #pragma unroll 4
        for (int i = 0; i < FEAT; i++) {
            float4 w = W4[i * 32 + lane];     // W_out[i][lane*4 .. lane*4+3]
            float f0 = fw[i];
            float f1 = fw[256 + i];
            a0.x = fmaf(f0, w.x, a0.x); a0.y = fmaf(f0, w.y, a0.y);
            a0.z = fmaf(f0, w.z, a0.z); a0.w = fmaf(f0, w.w, a0.w);
            a1.x = fmaf(f1, w.x, a1.x); a1.y = fmaf(f1, w.y, a1.y);
            a1.z = fmaf(f1, w.z, a1.z); a1.w = fmaf(f1, w.w, a1.w);
        }
        float4 o0, o1;
        o0.x = fmaxf(a0.x + bo.x, 0.f); o0.y = fmaxf(a0.y + bo.y, 0.f);
        o0.z = fmaxf(a0.z + bo.z, 0.f); o0.w = fmaxf(a0.w + bo.w, 0.f);
        o1.x = fmaxf(a1.x + bo.x, 0.f); o1.y = fmaxf(a1.y + bo.y, 0.f);
        o1.z = fmaxf(a1.z + bo.z, 0.f); o1.w = fmaxf(a1.w + bo.w, 0.f);
        ((float4*)out)[(size_t)r0 * 32 + lane]       = o0;
        ((float4*)out)[(size_t)(r0 + 1) * 32 + lane] = o1;
        __syncwarp();
    }
}

// ---------------------------------------------------------------------------
extern "C" void kernel_launch(void* const* d_in, const int* in_sizes, int n_in,
                              void* d_out, int out_size)
{
    const float* x     = (const float*)d_in[0];
    const float* W_s   = (const float*)d_in[1];
    const float* b_s   = (const float*)d_in[2];
    const float* W_h   = (const float*)d_in[3];
    const float* b_h   = (const float*)d_in[4];
    const float* W_out = (const float*)d_in[5];
    const float* b_out = (const float*)d_in[6];
    // d_in[7] = batch (int64) — graphs are equal-size & sorted; unused.
    float* out = (float*)d_out;

    // k3 dynamic shared: W_out (128 KB) + per-warp feats (32 KB)
    int k3_smem = (FEAT * OUTF + 16 * 512) * (int)sizeof(float);
    cudaFuncSetAttribute(k3_out, cudaFuncAttributeMaxDynamicSharedMemorySize, k3_smem);

    k1_embed<<<512, 256>>>(x, W_s, b_s, W_h, b_h);
    k2_knn_agg<<<NB * (LG / 4), 128>>>();
    k3_out<<<148, 512, k3_smem>>>(x, W_out, b_out, out);
}

// round 3
// speedup vs baseline: 2.7683x; 2.7683x over previous
#include <cuda_runtime.h>
#include <math.h>

#define NB 64
#define LG 1024
#define NN (NB*LG)
#define KK 16
#define INF_ 128
#define OUTF 128
#define SS 4
#define FLR 64
#define FEAT 256

// Scratch (device globals: allocation is forbidden)
__device__ float g_s[NN * SS];
__device__ float g_h[NN * FLR];
__device__ float g_agg[NN * 2 * FLR];

// ---------------------------------------------------------------------------
// Kernel 1: s = x@W_s + b_s  (N,4) and h = x@W_h + b_h (N,64).
// 8 rows per warp: weight LDS amortized 8x, x rows staged in padded shared
// (stride 132 -> conflict-free multi-row broadcast).
// ---------------------------------------------------------------------------
#define K1_RS 132
__global__ __launch_bounds__(256) void k1_embed(
    const float* __restrict__ x,
    const float* __restrict__ Ws, const float* __restrict__ bs,
    const float* __restrict__ Wh, const float* __restrict__ bh)
{
    extern __shared__ float sm1[];
    float* sWh = sm1;                  // 128*64
    float* sWs = sWh + INF_ * FLR;     // 128*4
    float* sbh = sWs + INF_ * SS;      // 64
    float* sbs = sbh + FLR;            // 8 (padded)
    float* sxb = sbs + 8;              // 8 warps * 8 rows * 132

    int tid = threadIdx.x;
    for (int i = tid; i < INF_ * FLR; i += 256) sWh[i] = Wh[i];
    for (int i = tid; i < INF_ * SS;  i += 256) sWs[i] = Ws[i];
    if (tid < FLR) sbh[tid] = bh[tid];
    if (tid < SS)  sbs[tid] = bs[tid];
    __syncthreads();

    int warp = tid >> 5, lane = tid & 31;
    int rowbase = blockIdx.x * 64 + warp * 8;
    float* xw = sxb + warp * (8 * K1_RS);

    #pragma unroll
    for (int r = 0; r < 8; r++) {
        const float4* xr = (const float4*)(x + (size_t)(rowbase + r) * INF_);
        ((float4*)(xw + r * K1_RS))[lane] = xr[lane];
    }
    __syncwarp();

    float a0[8], a1[8];
    #pragma unroll
    for (int r = 0; r < 8; r++) { a0[r] = 0.f; a1[r] = 0.f; }
    float as = 0.f;
    int rsel = lane >> 2, sdim = lane & 3;
    const float* xsrow = xw + rsel * K1_RS;

    #pragma unroll 4
    for (int i = 0; i < INF_; i++) {
        float w0  = sWh[i * FLR + lane];
        float w1  = sWh[i * FLR + 32 + lane];
        float wsv = sWs[i * SS + sdim];
        as = fmaf(xsrow[i], wsv, as);
        #pragma unroll
        for (int r = 0; r < 8; r++) {
            float xv = xw[r * K1_RS + i];
            a0[r] = fmaf(xv, w0, a0[r]);
            a1[r] = fmaf(xv, w1, a1[r]);
        }
    }
    #pragma unroll
    for (int r = 0; r < 8; r++) {
        g_h[(size_t)(rowbase + r) * FLR + lane]      = a0[r] + sbh[lane];
        g_h[(size_t)(rowbase + r) * FLR + 32 + lane] = a1[r] + sbh[32 + lane];
    }
    g_s[(size_t)(rowbase + rsel) * SS + sdim] = as + sbs[sdim];
}

// ---------------------------------------------------------------------------
// Kernel 2: per-graph kNN + aggregate. d2 row lives in REGISTERS (32/lane).
// Selection: 16 strictly-ascending value-extraction passes on the uint image
// of d2 (positive floats are order-isomorphic as uint) -> 3 ALU ops/elem,
// zero LDS, full precision. Indices recovered by one ballot-compaction pass
// against T (16th smallest), ascending j = reference's stable tie-break.
// ---------------------------------------------------------------------------
__global__ __launch_bounds__(256) void k2_knn_agg()
{
    __shared__ float4 s_sh[LG];         // 16 KB
    __shared__ float  sq_sh[LG];        // 4 KB
    __shared__ int    sel_j[8][KK];
    __shared__ float  sel_d[8][KK];

    int g  = blockIdx.x >> 7;           // 128 blocks per graph (8 nodes each)
    int nb = blockIdx.x & 127;
    int tid = threadIdx.x, warp = tid >> 5, lane = tid & 31;
    int gbase = g * LG;

    const float4* sg = (const float4*)(g_s + (size_t)gbase * SS);
    for (int i = tid; i < LG; i += 256) {
        float4 v = sg[i];
        s_sh[i] = v;
        sq_sh[i] = v.x*v.x + v.y*v.y + v.z*v.z + v.w*v.w;
    }
    __syncthreads();

    int li = nb * 8 + warp;
    float4 si = s_sh[li];
    float sqi = sq_sh[li];

    unsigned u[32];
    #pragma unroll
    for (int c = 0; c < 32; c++) {
        int j = (c << 5) | lane;
        float4 sj = s_sh[j];
        float dot = si.x*sj.x + si.y*sj.y + si.z*sj.z + si.w*sj.w;
        float v = fmaxf(sqi + sq_sh[j] - 2.f * dot, 0.f);
        u[c] = __float_as_uint(v);
    }

    // 16 ascending extraction passes (values only, exact)
    int prevI = -1;
    unsigned T = 0;
    #pragma unroll 1
    for (int t = 0; t < KK; t++) {
        unsigned best = 0xFFFFFFFFu;
        #pragma unroll
        for (int c = 0; c < 32; c++) {
            unsigned cand = ((int)u[c] > prevI) ? u[c] : 0xFFFFFFFFu;
            best = min(best, cand);
        }
        #pragma unroll
        for (int off = 16; off; off >>= 1)
            best = min(best, __shfl_xor_sync(0xffffffffu, best, off));
        prevI = (int)best;
        T = best;
    }

    // compact indices with u <= T (ascending j, capped at 16)
    int TI = (int)T;
    int base = 0;
    unsigned lmask = (1u << lane) - 1u;
    #pragma unroll
    for (int c = 0; c < 32; c++) {
        bool p = ((int)u[c] <= TI);
        unsigned m = __ballot_sync(0xffffffffu, p);
        if (p) {
            int pos = base + __popc(m & lmask);
            if (pos < KK) {
                sel_j[warp][pos] = (c << 5) | lane;
                sel_d[warp][pos] = __uint_as_float(u[c]);
            }
        }
        base += __popc(m);
    }
    __syncwarp();

    // gather + weighted mean/max (lane handles dims lane, lane+32)
    float m0 = 0.f, m1 = 0.f, x0 = -3.4e38f, x1 = -3.4e38f;
    #pragma unroll 1
    for (int t = 0; t < KK; t++) {
        int   j  = sel_j[warp][t];
        float wt = __expf(-10.f * sel_d[warp][t]);
        const float* hp = g_h + (size_t)(gbase + j) * FLR;
        float v0 = hp[lane]      * wt;
        float v1 = hp[lane + 32] * wt;
        m0 += v0; m1 += v1;
        x0 = fmaxf(x0, v0); x1 = fmaxf(x1, v1);
    }
    float* ap = g_agg + (size_t)(gbase + li) * (2 * FLR);
    ap[lane]      = m0 * (1.f / 16.f);
    ap[lane + 32] = m1 * (1.f / 16.f);
    ap[64 + lane] = x0;
    ap[96 + lane] = x1;
}

// ---------------------------------------------------------------------------
// Kernel 3: out = relu([x | agg] @ W_out + b_out).
// 4 rows/warp, float4 feature loads: 8 LDS.128 feed 64 FMA per step
// (crossbar balanced against the FFMA floor). W_out + staged feats in shared.
// ---------------------------------------------------------------------------
__global__ __launch_bounds__(512) void k3_out(
    const float* __restrict__ x,
    const float* __restrict__ Wout, const float* __restrict__ bout,
    float* __restrict__ out)
{
    extern __shared__ float sm3[];
    float* Wsh = sm3;                       // 256*128 floats (128 KB)
    float* fb  = sm3 + FEAT * OUTF;         // 16 warps * 4 rows * 256 (64 KB)

    int tid = threadIdx.x;
    {
        const float4* Wg = (const float4*)Wout;
        float4* Wd = (float4*)Wsh;
        for (int i = tid; i < FEAT * OUTF / 4; i += 512) Wd[i] = Wg[i];
    }
    __syncthreads();

    int warp = tid >> 5, lane = tid & 31;
    float4* F4 = (float4*)(fb + warp * (4 * FEAT));
    const float4* W4 = (const float4*)Wsh;
    float4 bo = ((const float4*)bout)[lane];

    for (int grp = blockIdx.x * 16 + warp; grp < NN / 4; grp += gridDim.x * 16) {
        int r0 = grp * 4;
        #pragma unroll
        for (int r = 0; r < 4; r++) {
            F4[r * 64 + lane]      = ((const float4*)(x     + (size_t)(r0 + r) * INF_))[lane];
            F4[r * 64 + 32 + lane] = ((const float4*)(g_agg + (size_t)(r0 + r) * (2 * FLR)))[lane];
        }
        __syncwarp();

        float4 acc[4];
        #pragma unroll
        for (int r = 0; r < 4; r++) acc[r] = make_float4(0.f, 0.f, 0.f, 0.f);

        #pragma unroll 2
        for (int i = 0; i < FEAT; i += 4) {
            float4 w0 = W4[(i + 0) * 32 + lane];
            float4 w1 = W4[(i + 1) * 32 + lane];
            float4 w2 = W4[(i + 2) * 32 + lane];
            float4 w3 = W4[(i + 3) * 32 + lane];
            #pragma unroll
            for (int r = 0; r < 4; r++) {
                float4 f = F4[r * 64 + (i >> 2)];
                acc[r].x = fmaf(f.x, w0.x, acc[r].x); acc[r].y = fmaf(f.x, w0.y, acc[r].y);
                acc[r].z = fmaf(f.x, w0.z, acc[r].z); acc[r].w = fmaf(f.x, w0.w, acc[r].w);
                acc[r].x = fmaf(f.y, w1.x, acc[r].x); acc[r].y = fmaf(f.y, w1.y, acc[r].y);
                acc[r].z = fmaf(f.y, w1.z, acc[r].z); acc[r].w = fmaf(f.y, w1.w, acc[r].w);
                acc[r].x = fmaf(f.z, w2.x, acc[r].x); acc[r].y = fmaf(f.z, w2.y, acc[r].y);
                acc[r].z = fmaf(f.z, w2.z, acc[r].z); acc[r].w = fmaf(f.z, w2.w, acc[r].w);
                acc[r].x = fmaf(f.w, w3.x, acc[r].x); acc[r].y = fmaf(f.w, w3.y, acc[r].y);
                acc[r].z = fmaf(f.w, w3.z, acc[r].z); acc[r].w = fmaf(f.w, w3.w, acc[r].w);
            }
        }
        #pragma unroll
        for (int r = 0; r < 4; r++) {
            float4 o;
            o.x = fmaxf(acc[r].x + bo.x, 0.f);
            o.y = fmaxf(acc[r].y + bo.y, 0.f);
            o.z = fmaxf(acc[r].z + bo.z, 0.f);
            o.w = fmaxf(acc[r].w + bo.w, 0.f);
            ((float4*)out)[(size_t)(r0 + r) * 32 + lane] = o;
        }
        __syncwarp();
    }
}

// ---------------------------------------------------------------------------
extern "C" void kernel_launch(void* const* d_in, const int* in_sizes, int n_in,
                              void* d_out, int out_size)
{
    const float* x     = (const float*)d_in[0];
    const float* W_s   = (const float*)d_in[1];
    const float* b_s   = (const float*)d_in[2];
    const float* W_h   = (const float*)d_in[3];
    const float* b_h   = (const float*)d_in[4];
    const float* W_out = (const float*)d_in[5];
    const float* b_out = (const float*)d_in[6];
    // d_in[7] = batch (int64) — equal-size sorted graphs; unused.
    float* out = (float*)d_out;

    int k1_smem = (INF_ * FLR + INF_ * SS + FLR + 8 + 8 * 8 * K1_RS) * (int)sizeof(float);
    int k3_smem = (FEAT * OUTF + 16 * 4 * FEAT) * (int)sizeof(float);
    cudaFuncSetAttribute(k1_embed, cudaFuncAttributeMaxDynamicSharedMemorySize, k1_smem);
    cudaFuncSetAttribute(k3_out,   cudaFuncAttributeMaxDynamicSharedMemorySize, k3_smem);

    k1_embed<<<NN / 64, 256, k1_smem>>>(x, W_s, b_s, W_h, b_h);
    k2_knn_agg<<<NB * (LG / 8), 256>>>();
    k3_out<<<148, 512, k3_smem>>>(x, W_out, b_out, out);
}

// round 10
// speedup vs baseline: 3.2460x; 1.1726x over previous
#include <cuda_runtime.h>
#include <cuda_bf16.h>
#include <math.h>
#include <stdint.h>

#define NB 64
#define LG 1024
#define NN (NB*LG)
#define KK 16
#define INF_ 128
#define OUTF 128
#define SS 4
#define FLR 64
#define FEAT 256

// Scratch (device globals: allocation is forbidden)
__device__ float g_s[NN * SS];
__device__ float g_h[NN * FLR];
__device__ float g_agg[NN * 2 * FLR];

// ---------------------------------------------------------------------------
// Kernel 1 (unchanged): s = x@W_s + b_s, h = x@W_h + b_h. 8 rows/warp.
// ---------------------------------------------------------------------------
#define K1_RS 132
__global__ __launch_bounds__(256) void k1_embed(
    const float* __restrict__ x,
    const float* __restrict__ Ws, const float* __restrict__ bs,
    const float* __restrict__ Wh, const float* __restrict__ bh)
{
    extern __shared__ float sm1[];
    float* sWh = sm1;
    float* sWs = sWh + INF_ * FLR;
    float* sbh = sWs + INF_ * SS;
    float* sbs = sbh + FLR;
    float* sxb = sbs + 8;

    int tid = threadIdx.x;
    for (int i = tid; i < INF_ * FLR; i += 256) sWh[i] = Wh[i];
    for (int i = tid; i < INF_ * SS;  i += 256) sWs[i] = Ws[i];
    if (tid < FLR) sbh[tid] = bh[tid];
    if (tid < SS)  sbs[tid] = bs[tid];
    __syncthreads();

    int warp = tid >> 5, lane = tid & 31;
    int rowbase = blockIdx.x * 64 + warp * 8;
    float* xw = sxb + warp * (8 * K1_RS);

    #pragma unroll
    for (int r = 0; r < 8; r++) {
        const float4* xr = (const float4*)(x + (size_t)(rowbase + r) * INF_);
        ((float4*)(xw + r * K1_RS))[lane] = xr[lane];
    }
    __syncwarp();

    float a0[8], a1[8];
    #pragma unroll
    for (int r = 0; r < 8; r++) { a0[r] = 0.f; a1[r] = 0.f; }
    float as = 0.f;
    int rsel = lane >> 2, sdim = lane & 3;
    const float* xsrow = xw + rsel * K1_RS;

    #pragma unroll 4
    for (int i = 0; i < INF_; i++) {
        float w0  = sWh[i * FLR + lane];
        float w1  = sWh[i * FLR + 32 + lane];
        float wsv = sWs[i * SS + sdim];
        as = fmaf(xsrow[i], wsv, as);
        #pragma unroll
        for (int r = 0; r < 8; r++) {
            float xv = xw[r * K1_RS + i];
            a0[r] = fmaf(xv, w0, a0[r]);
            a1[r] = fmaf(xv, w1, a1[r]);
        }
    }
    #pragma unroll
    for (int r = 0; r < 8; r++) {
        g_h[(size_t)(rowbase + r) * FLR + lane]      = a0[r] + sbh[lane];
        g_h[(size_t)(rowbase + r) * FLR + 32 + lane] = a1[r] + sbh[32 + lane];
    }
    g_s[(size_t)(rowbase + rsel) * SS + sdim] = as + sbs[sdim];
}

// ---------------------------------------------------------------------------
// Kernel 2 (unchanged): per-graph kNN + aggregate.
// ---------------------------------------------------------------------------
__global__ __launch_bounds__(256) void k2_knn_agg()
{
    __shared__ float4 s_sh[LG];
    __shared__ float  sq_sh[LG];
    __shared__ int    sel_j[8][KK];
    __shared__ float  sel_d[8][KK];

    int g  = blockIdx.x >> 7;
    int nb = blockIdx.x & 127;
    int tid = threadIdx.x, warp = tid >> 5, lane = tid & 31;
    int gbase = g * LG;

    const float4* sg = (const float4*)(g_s + (size_t)gbase * SS);
    for (int i = tid; i < LG; i += 256) {
        float4 v = sg[i];
        s_sh[i] = v;
        sq_sh[i] = v.x*v.x + v.y*v.y + v.z*v.z + v.w*v.w;
    }
    __syncthreads();

    int li = nb * 8 + warp;
    float4 si = s_sh[li];
    float sqi = sq_sh[li];

    unsigned u[32];
    #pragma unroll
    for (int c = 0; c < 32; c++) {
        int j = (c << 5) | lane;
        float4 sj = s_sh[j];
        float dot = si.x*sj.x + si.y*sj.y + si.z*sj.z + si.w*sj.w;
        float v = fmaxf(sqi + sq_sh[j] - 2.f * dot, 0.f);
        u[c] = __float_as_uint(v);
    }

    int prevI = -1;
    unsigned T = 0;
    #pragma unroll 1
    for (int t = 0; t < KK; t++) {
        unsigned best = 0xFFFFFFFFu;
        #pragma unroll
        for (int c = 0; c < 32; c++) {
            unsigned cand = ((int)u[c] > prevI) ? u[c] : 0xFFFFFFFFu;
            best = min(best, cand);
        }
        #pragma unroll
        for (int off = 16; off; off >>= 1)
            best = min(best, __shfl_xor_sync(0xffffffffu, best, off));
        prevI = (int)best;
        T = best;
    }

    int TI = (int)T;
    int base = 0;
    unsigned lmask = (1u << lane) - 1u;
    #pragma unroll
    for (int c = 0; c < 32; c++) {
        bool p = ((int)u[c] <= TI);
        unsigned m = __ballot_sync(0xffffffffu, p);
        if (p) {
            int pos = base + __popc(m & lmask);
            if (pos < KK) {
                sel_j[warp][pos] = (c << 5) | lane;
                sel_d[warp][pos] = __uint_as_float(u[c]);
            }
        }
        base += __popc(m);
    }
    __syncwarp();

    float m0 = 0.f, m1 = 0.f, x0 = -3.4e38f, x1 = -3.4e38f;
    #pragma unroll 1
    for (int t = 0; t < KK; t++) {
        int   j  = sel_j[warp][t];
        float wt = __expf(-10.f * sel_d[warp][t]);
        const float* hp = g_h + (size_t)(gbase + j) * FLR;
        float v0 = hp[lane]      * wt;
        float v1 = hp[lane + 32] * wt;
        m0 += v0; m1 += v1;
        x0 = fmaxf(x0, v0); x1 = fmaxf(x1, v1);
    }
    float* ap = g_agg + (size_t)(gbase + li) * (2 * FLR);
    ap[lane]      = m0 * (1.f / 16.f);
    ap[lane + 32] = m1 * (1.f / 16.f);
    ap[64 + lane] = x0;
    ap[96 + lane] = x1;
}

// ---------------------------------------------------------------------------
// Kernel 3: HMMA (mma.sync m16n8k16 bf16) GEMM, bf16x3 precision.
//   out = relu([x|agg] @ W + b)
// CTA: 256 thr = 8 warps (4x2), tile 128x128, K=256 from padded shared.
// Works on compute_103 (no tcgen05 needed).
// ---------------------------------------------------------------------------
#define K3_BROW 528                     // 264 bf16 per row (8-elem pad)
#define K3_BHI  0
#define K3_BLO  67584
#define K3_A    135168
#define K3_SMEM 202752

__device__ __forceinline__ uint32_t s2u(const void* p) {
    uint32_t a;
    asm("{ .reg .u64 t; cvta.to.shared.u64 t, %1; cvt.u32.u64 %0, t; }" : "=r"(a) : "l"(p));
    return a;
}
__device__ __forceinline__ uint32_t pk_hi(float a, float b) {
    uint32_t p;
    asm("cvt.rn.bf16x2.f32 %0, %1, %2;" : "=r"(p) : "f"(b), "f"(a));
    return p;   // low16 = bf16(a), high16 = bf16(b)
}
__device__ __forceinline__ uint32_t pk_lo(float a, float b) {
    uint32_t p = pk_hi(a, b);
    float ha = __uint_as_float(p << 16);
    float hb = __uint_as_float(p & 0xFFFF0000u);
    return pk_hi(a - ha, b - hb);
}
__device__ __forceinline__ void sts128(uint32_t addr, uint32_t a, uint32_t b, uint32_t c, uint32_t d) {
    asm volatile("st.shared.v4.b32 [%0], {%1,%2,%3,%4};" :: "r"(addr), "r"(a), "r"(b), "r"(c), "r"(d) : "memory");
}
__device__ __forceinline__ void st32(uint32_t addr, uint32_t v) {
    asm volatile("st.shared.b32 [%0], %1;" :: "r"(addr), "r"(v) : "memory");
}
__device__ __forceinline__ void ldsm4(uint32_t* r, uint32_t addr) {
    asm volatile("ldmatrix.sync.aligned.m8n8.x4.shared.b16 {%0,%1,%2,%3}, [%4];"
        : "=r"(r[0]), "=r"(r[1]), "=r"(r[2]), "=r"(r[3]) : "r"(addr));
}
__device__ __forceinline__ void mma16816(float* c, const uint32_t* a, uint32_t b0, uint32_t b1) {
    asm volatile("mma.sync.aligned.m16n8k16.row.col.f32.bf16.bf16.f32 "
        "{%0,%1,%2,%3}, {%4,%5,%6,%7}, {%8,%9}, {%0,%1,%2,%3};"
        : "+f"(c[0]), "+f"(c[1]), "+f"(c[2]), "+f"(c[3])
        : "r"(a[0]), "r"(a[1]), "r"(a[2]), "r"(a[3]), "r"(b0), "r"(b1));
}

__global__ __launch_bounds__(256, 1) void k3_mma(
    const float* __restrict__ x,
    const float* __restrict__ Wout, const float* __restrict__ bout,
    float* __restrict__ out)
{
    extern __shared__ __align__(16) char smem[];
    uint32_t sb = s2u(smem);
    int tid = threadIdx.x, warp = tid >> 5, lane = tid & 31;
    int wm = warp >> 1, wn = warp & 1;

    // ---- one-time: B = W^T (hi/lo split) into smem, layout [n][k] padded ----
    for (int i = tid; i < 128 * 128; i += 256) {
        int n = i & 127, k0 = (i >> 7) * 2;
        float w0 = Wout[(size_t)k0 * OUTF + n];
        float w1 = Wout[(size_t)(k0 + 1) * OUTF + n];
        uint32_t ph = pk_hi(w0, w1);
        float h0 = __uint_as_float(ph << 16);
        float h1 = __uint_as_float(ph & 0xFFFF0000u);
        uint32_t pl = pk_hi(w0 - h0, w1 - h1);
        uint32_t off = (uint32_t)n * K3_BROW + (uint32_t)k0 * 2;
        st32(sb + K3_BHI + off, ph);
        st32(sb + K3_BLO + off, pl);
    }

    // bias fragments (col = wn*64 + f*8 + (lane&3)*2)
    float2 bias[8];
    #pragma unroll
    for (int f = 0; f < 8; f++)
        bias[f] = *(const float2*)(bout + wn * 64 + f * 8 + (lane & 3) * 2);

    // ldmatrix base addresses
    uint32_t aAddr[2];
    #pragma unroll
    for (int mi = 0; mi < 2; mi++)
        aAddr[mi] = sb + K3_A
                  + (uint32_t)(wm * 32 + mi * 16 + (lane & 15)) * K3_BROW
                  + (uint32_t)((lane >> 4) * 16);
    uint32_t bRow = (uint32_t)(wn * 64 + (lane & 7) + ((lane >> 4) << 3)) * K3_BROW
                  + (uint32_t)(((lane >> 3) & 1) * 16);

    for (int t = 0; t < 4; t++) {
        int r0 = (blockIdx.x * 4 + t) * 128;
        float c[2][8][4];
        #pragma unroll
        for (int mi = 0; mi < 2; mi++)
            #pragma unroll
            for (int f = 0; f < 8; f++)
                #pragma unroll
                for (int q = 0; q < 4; q++) c[mi][f][q] = 0.f;

        // ---- convert A_hi: feats tile -> bf16 smem ----
        __syncthreads();   // prev tile readers / B build done
        #pragma unroll 4
        for (int c2 = tid; c2 < 4096; c2 += 256) {
            int half = c2 >> 11;
            int fidx = (c2 & 2047) * 8;
            int row = fidx >> 7, kk2 = fidx & 127;
            const float* gp = (half ? g_agg : x) + (size_t)(r0 + row) * 128 + kk2;
            float4 v0 = ((const float4*)gp)[0];
            float4 v1 = ((const float4*)gp)[1];
            sts128(sb + K3_A + (uint32_t)row * K3_BROW + (uint32_t)(kk2 + half * 128) * 2,
                   pk_hi(v0.x, v0.y), pk_hi(v0.z, v0.w),
                   pk_hi(v1.x, v1.y), pk_hi(v1.z, v1.w));
        }
        __syncthreads();

        // ---- pass 1: A_hi x B_hi  +  A_hi x B_lo ----
        #pragma unroll
        for (int ks = 0; ks < 16; ks++) {
            uint32_t koff = (uint32_t)ks * 32;
            uint32_t a[2][4], bh[4][4], bl[4][4];
            ldsm4(a[0], aAddr[0] + koff);
            ldsm4(a[1], aAddr[1] + koff);
            #pragma unroll
            for (int j2 = 0; j2 < 4; j2++) {
                uint32_t ro = bRow + (uint32_t)j2 * (16 * K3_BROW) + koff;
                ldsm4(bh[j2], sb + K3_BHI + ro);
                ldsm4(bl[j2], sb + K3_BLO + ro);
            }
            #pragma unroll
            for (int mi = 0; mi < 2; mi++)
                #pragma unroll
                for (int f = 0; f < 8; f++) {
                    mma16816(c[mi][f], a[mi], bh[f >> 1][(f & 1) * 2], bh[f >> 1][(f & 1) * 2 + 1]);
                    mma16816(c[mi][f], a[mi], bl[f >> 1][(f & 1) * 2], bl[f >> 1][(f & 1) * 2 + 1]);
                }
        }
        __syncthreads();

        // ---- convert A_lo (overwrite) ----
        #pragma unroll 4
        for (int c2 = tid; c2 < 4096; c2 += 256) {
            int half = c2 >> 11;
            int fidx = (c2 & 2047) * 8;
            int row = fidx >> 7, kk2 = fidx & 127;
            const float* gp = (half ? g_agg : x) + (size_t)(r0 + row) * 128 + kk2;
            float4 v0 = ((const float4*)gp)[0];
            float4 v1 = ((const float4*)gp)[1];
            sts128(sb + K3_A + (uint32_t)row * K3_BROW + (uint32_t)(kk2 + half * 128) * 2,
                   pk_lo(v0.x, v0.y), pk_lo(v0.z, v0.w),
                   pk_lo(v1.x, v1.y), pk_lo(v1.z, v1.w));
        }
        __syncthreads();

        // ---- pass 2: A_lo x B_hi ----
        #pragma unroll
        for (int ks = 0; ks < 16; ks++) {
            uint32_t koff = (uint32_t)ks * 32;
            uint32_t a[2][4], bh[4][4];
            ldsm4(a[0], aAddr[0] + koff);
            ldsm4(a[1], aAddr[1] + koff);
            #pragma unroll
            for (int j2 = 0; j2 < 4; j2++)
                ldsm4(bh[j2], sb + K3_BHI + bRow + (uint32_t)j2 * (16 * K3_BROW) + koff);
            #pragma unroll
            for (int mi = 0; mi < 2; mi++)
                #pragma unroll
                for (int f = 0; f < 8; f++)
                    mma16816(c[mi][f], a[mi], bh[f >> 1][(f & 1) * 2], bh[f >> 1][(f & 1) * 2 + 1]);
        }

        // ---- epilogue: bias + relu + direct STG from fragments ----
        #pragma unroll
        for (int mi = 0; mi < 2; mi++) {
            int row = r0 + wm * 32 + mi * 16 + (lane >> 2);
            #pragma unroll
            for (int f = 0; f < 8; f++) {
                int col = wn * 64 + f * 8 + (lane & 3) * 2;
                float2 v0, v1;
                v0.x = fmaxf(c[mi][f][0] + bias[f].x, 0.f);
                v0.y = fmaxf(c[mi][f][1] + bias[f].y, 0.f);
                v1.x = fmaxf(c[mi][f][2] + bias[f].x, 0.f);
                v1.y = fmaxf(c[mi][f][3] + bias[f].y, 0.f);
                *(float2*)(out + (size_t)row * OUTF + col)       = v0;
                *(float2*)(out + (size_t)(row + 8) * OUTF + col) = v1;
            }
        }
    }
}

// ---------------------------------------------------------------------------
extern "C" void kernel_launch(void* const* d_in, const int* in_sizes, int n_in,
                              void* d_out, int out_size)
{
    const float* x     = (const float*)d_in[0];
    const float* W_s   = (const float*)d_in[1];
    const float* b_s   = (const float*)d_in[2];
    const float* W_h   = (const float*)d_in[3];
    const float* b_h   = (const float*)d_in[4];
    const float* W_out = (const float*)d_in[5];
    const float* b_out = (const float*)d_in[6];
    // d_in[7] = batch (int64) — equal-size sorted graphs; unused.
    float* out = (float*)d_out;

    int k1_smem = (INF_ * FLR + INF_ * SS + FLR + 8 + 8 * 8 * K1_RS) * (int)sizeof(float);
    cudaFuncSetAttribute(k1_embed, cudaFuncAttributeMaxDynamicSharedMemorySize, k1_smem);
    cudaFuncSetAttribute(k3_mma,   cudaFuncAttributeMaxDynamicSharedMemorySize, K3_SMEM);

    k1_embed<<<NN / 64, 256, k1_smem>>>(x, W_s, b_s, W_h, b_h);
    k2_knn_agg<<<NB * (LG / 8), 256>>>();
    k3_mma<<<128, 256, K3_SMEM>>>(x, W_out, b_out, out);
}

// round 11
// speedup vs baseline: 3.9521x; 1.2175x over previous
#include <cuda_runtime.h>
#include <cuda_bf16.h>
#include <math.h>
#include <stdint.h>

#define NB 64
#define LG 1024
#define NN (NB*LG)
#define KK 16
#define INF_ 128
#define OUTF 128
#define SS 4
#define FLR 64
#define FEAT 256

// Scratch (device globals: allocation is forbidden)
__device__ float g_s[NN * SS];
__device__ float g_h[NN * FLR];
__device__ float g_agg[NN * 2 * FLR];
__device__ uint32_t g_Wbhi[128 * 128];   // W^T bf16-hi, [n][kw] packed 2/word
__device__ uint32_t g_Wblo[128 * 128];   // W^T bf16-lo

// ---------------------------------------------------------------------------
// helpers
// ---------------------------------------------------------------------------
__device__ __forceinline__ uint32_t s2u(const void* p) {
    uint32_t a;
    asm("{ .reg .u64 t; cvta.to.shared.u64 t, %1; cvt.u32.u64 %0, t; }" : "=r"(a) : "l"(p));
    return a;
}
__device__ __forceinline__ uint32_t pk_hi(float a, float b) {
    uint32_t p;
    asm("cvt.rn.bf16x2.f32 %0, %1, %2;" : "=r"(p) : "f"(b), "f"(a));
    return p;   // low16 = bf16(a), high16 = bf16(b)
}
__device__ __forceinline__ uint32_t pk_lo_from(uint32_t ph, float a, float b) {
    float ha = __uint_as_float(ph << 16);
    float hb = __uint_as_float(ph & 0xFFFF0000u);
    return pk_hi(a - ha, b - hb);
}
__device__ __forceinline__ void sts128(uint32_t addr, uint32_t a, uint32_t b, uint32_t c, uint32_t d) {
    asm volatile("st.shared.v4.b32 [%0], {%1,%2,%3,%4};" :: "r"(addr), "r"(a), "r"(b), "r"(c), "r"(d) : "memory");
}
__device__ __forceinline__ void ldsm4(uint32_t* r, uint32_t addr) {
    asm volatile("ldmatrix.sync.aligned.m8n8.x4.shared.b16 {%0,%1,%2,%3}, [%4];"
        : "=r"(r[0]), "=r"(r[1]), "=r"(r[2]), "=r"(r[3]) : "r"(addr));
}
__device__ __forceinline__ void mma16816(float* c, const uint32_t* a, uint32_t b0, uint32_t b1) {
    asm volatile("mma.sync.aligned.m16n8k16.row.col.f32.bf16.bf16.f32 "
        "{%0,%1,%2,%3}, {%4,%5,%6,%7}, {%8,%9}, {%0,%1,%2,%3};"
        : "+f"(c[0]), "+f"(c[1]), "+f"(c[2]), "+f"(c[3])
        : "r"(a[0]), "r"(a[1]), "r"(a[2]), "r"(a[3]), "r"(b0), "r"(b1));
}

// ---------------------------------------------------------------------------
// Kernel 0: W_out -> bf16 hi/lo split, B layout [n][k] (one-time, tiny)
// ---------------------------------------------------------------------------
__global__ __launch_bounds__(256) void k0_convW(const float* __restrict__ Wout)
{
    int idx = blockIdx.x * 256 + threadIdx.x;   // 0..16383 words
    int n = idx >> 7, kw = idx & 127;
    float w0 = Wout[(size_t)(2 * kw) * OUTF + n];
    float w1 = Wout[(size_t)(2 * kw + 1) * OUTF + n];
    uint32_t ph = pk_hi(w0, w1);
    g_Wbhi[idx] = ph;
    g_Wblo[idx] = pk_lo_from(ph, w0, w1);
}

// ---------------------------------------------------------------------------
// Kernel 1 (unchanged): s = x@W_s + b_s, h = x@W_h + b_h. 8 rows/warp.
// ---------------------------------------------------------------------------
#define K1_RS 132
__global__ __launch_bounds__(256) void k1_embed(
    const float* __restrict__ x,
    const float* __restrict__ Ws, const float* __restrict__ bs,
    const float* __restrict__ Wh, const float* __restrict__ bh)
{
    extern __shared__ float sm1[];
    float* sWh = sm1;
    float* sWs = sWh + INF_ * FLR;
    float* sbh = sWs + INF_ * SS;
    float* sbs = sbh + FLR;
    float* sxb = sbs + 8;

    int tid = threadIdx.x;
    for (int i = tid; i < INF_ * FLR; i += 256) sWh[i] = Wh[i];
    for (int i = tid; i < INF_ * SS;  i += 256) sWs[i] = Ws[i];
    if (tid < FLR) sbh[tid] = bh[tid];
    if (tid < SS)  sbs[tid] = bs[tid];
    __syncthreads();

    int warp = tid >> 5, lane = tid & 31;
    int rowbase = blockIdx.x * 64 + warp * 8;
    float* xw = sxb + warp * (8 * K1_RS);

    #pragma unroll
    for (int r = 0; r < 8; r++) {
        const float4* xr = (const float4*)(x + (size_t)(rowbase + r) * INF_);
        ((float4*)(xw + r * K1_RS))[lane] = xr[lane];
    }
    __syncwarp();

    float a0[8], a1[8];
    #pragma unroll
    for (int r = 0; r < 8; r++) { a0[r] = 0.f; a1[r] = 0.f; }
    float as = 0.f;
    int rsel = lane >> 2, sdim = lane & 3;
    const float* xsrow = xw + rsel * K1_RS;

    #pragma unroll 4
    for (int i = 0; i < INF_; i++) {
        float w0  = sWh[i * FLR + lane];
        float w1  = sWh[i * FLR + 32 + lane];
        float wsv = sWs[i * SS + sdim];
        as = fmaf(xsrow[i], wsv, as);
        #pragma unroll
        for (int r = 0; r < 8; r++) {
            float xv = xw[r * K1_RS + i];
            a0[r] = fmaf(xv, w0, a0[r]);
            a1[r] = fmaf(xv, w1, a1[r]);
        }
    }
    #pragma unroll
    for (int r = 0; r < 8; r++) {
        g_h[(size_t)(rowbase + r) * FLR + lane]      = a0[r] + sbh[lane];
        g_h[(size_t)(rowbase + r) * FLR + 32 + lane] = a1[r] + sbh[32 + lane];
    }
    g_s[(size_t)(rowbase + rsel) * SS + sdim] = as + sbs[sdim];
}

// ---------------------------------------------------------------------------
// Kernel 2: per-graph kNN + aggregate. Successor-trick extraction:
// min(u - base) unsigned == min{u : u >= base}; base = prev+1. 2 ops/elem.
// ---------------------------------------------------------------------------
__global__ __launch_bounds__(256) void k2_knn_agg()
{
    __shared__ float4 s_sh[LG];
    __shared__ float  sq_sh[LG];
    __shared__ int    sel_j[8][KK];
    __shared__ float  sel_d[8][KK];

    int g  = blockIdx.x >> 7;
    int nb = blockIdx.x & 127;
    int tid = threadIdx.x, warp = tid >> 5, lane = tid & 31;
    int gbase = g * LG;

    const float4* sg = (const float4*)(g_s + (size_t)gbase * SS);
    for (int i = tid; i < LG; i += 256) {
        float4 v = sg[i];
        s_sh[i] = v;
        sq_sh[i] = v.x*v.x + v.y*v.y + v.z*v.z + v.w*v.w;
    }
    __syncthreads();

    int li = nb * 8 + warp;
    float4 si = s_sh[li];
    float sqi = sq_sh[li];

    unsigned u[32];
    #pragma unroll
    for (int c = 0; c < 32; c++) {
        int j = (c << 5) | lane;
        float4 sj = s_sh[j];
        float dot = si.x*sj.x + si.y*sj.y + si.z*sj.z + si.w*sj.w;
        float v = fmaxf(sqi + sq_sh[j] - 2.f * dot, 0.f);
        u[c] = __float_as_uint(v);
    }

    // 16 successor extractions: base-1 after pass t = t-th smallest value.
    // u < 2^31 (positive finite floats) => wrapped (u-base) > 2^31 separation.
    unsigned base = 0;
    #pragma unroll 1
    for (int t = 0; t < KK; t++) {
        unsigned m = 0xFFFFFFFFu;
        #pragma unroll
        for (int c = 0; c < 32; c++)
            m = min(m, u[c] - base);
        #pragma unroll
        for (int off = 16; off; off >>= 1)
            m = min(m, __shfl_xor_sync(0xffffffffu, m, off));
        base += m + 1u;
    }
    int TI = (int)(base - 1u);   // 16th smallest value (bits)

    // compact indices with u <= T (ascending j, capped at 16)
    int cbase = 0;
    unsigned lmask = (1u << lane) - 1u;
    #pragma unroll
    for (int c = 0; c < 32; c++) {
        bool p = ((int)u[c] <= TI);
        unsigned m = __ballot_sync(0xffffffffu, p);
        if (p) {
            int pos = cbase + __popc(m & lmask);
            if (pos < KK) {
                sel_j[warp][pos] = (c << 5) | lane;
                sel_d[warp][pos] = __uint_as_float(u[c]);
            }
        }
        cbase += __popc(m);
    }
    __syncwarp();

    float m0 = 0.f, m1 = 0.f, x0 = -3.4e38f, x1 = -3.4e38f;
    #pragma unroll 4
    for (int t = 0; t < KK; t++) {
        int   j  = sel_j[warp][t];
        float wt = __expf(-10.f * sel_d[warp][t]);
        const float* hp = g_h + (size_t)(gbase + j) * FLR;
        float v0 = hp[lane]      * wt;
        float v1 = hp[lane + 32] * wt;
        m0 += v0; m1 += v1;
        x0 = fmaxf(x0, v0); x1 = fmaxf(x1, v1);
    }
    float* ap = g_agg + (size_t)(gbase + li) * (2 * FLR);
    ap[lane]      = m0 * (1.f / 16.f);
    ap[lane + 32] = m1 * (1.f / 16.f);
    ap[64 + lane] = x0;
    ap[96 + lane] = x1;
}

// ---------------------------------------------------------------------------
// Kernel 3: HMMA bf16x3 GEMM, single-conversion fused-pass version.
//   A hi+lo built from ONE feats read per k-chunk (chunk0 = x, chunk1 = agg).
//   B hi/lo full-K resident in smem (staged from prebuilt global).
//   One kstep loop does hi*hi + hi*lo + lo*hi (48 MMA / 20 LDSM per kstep).
// ---------------------------------------------------------------------------
#define K3_AROW 272                 // 128 bf16 + 8 pad
#define K3_BROW 528                 // 256 bf16 + 8 pad
#define A_HI    0                   // 128*272 = 34816
#define A_LO    34816
#define B_HI    69632               // 128*528 = 67584
#define B_LO    137216
#define K3_SMEM 204800

__global__ __launch_bounds__(256, 1) void k3_mma(
    const float* __restrict__ x,
    const float* __restrict__ bout,
    float* __restrict__ out)
{
    extern __shared__ __align__(16) char smem[];
    uint32_t sb = s2u(smem);
    int tid = threadIdx.x, warp = tid >> 5, lane = tid & 31;
    int wm = warp >> 1, wn = warp & 1;

    // ---- stage B hi/lo (once per CTA, from prebuilt global) ----
    #pragma unroll 4
    for (int i = tid; i < 4096; i += 256) {     // 16B chunks
        uint4 vh = ((const uint4*)g_Wbhi)[i];
        uint4 vl = ((const uint4*)g_Wblo)[i];
        int n = i >> 5, c = i & 31;
        uint32_t off = (uint32_t)n * K3_BROW + (uint32_t)c * 16;
        sts128(sb + B_HI + off, vh.x, vh.y, vh.z, vh.w);
        sts128(sb + B_LO + off, vl.x, vl.y, vl.z, vl.w);
    }

    // bias fragments (col = wn*64 + f*8 + (lane&3)*2)
    float2 bias[8];
    #pragma unroll
    for (int f = 0; f < 8; f++)
        bias[f] = *(const float2*)(bout + wn * 64 + f * 8 + (lane & 3) * 2);

    // ldmatrix offsets (buffer-relative)
    uint32_t aoff[2];
    #pragma unroll
    for (int mi = 0; mi < 2; mi++)
        aoff[mi] = (uint32_t)(wm * 32 + mi * 16 + (lane & 15)) * K3_AROW
                 + (uint32_t)((lane >> 4) * 16);
    uint32_t boff = (uint32_t)(wn * 64 + (lane & 7) + ((lane >> 4) << 3)) * K3_BROW
                  + (uint32_t)(((lane >> 3) & 1) * 16);

    for (int t = blockIdx.x; t < NN / 128; t += gridDim.x) {
        int r0 = t * 128;
        float c[2][8][4];
        #pragma unroll
        for (int mi = 0; mi < 2; mi++)
            #pragma unroll
            for (int f = 0; f < 8; f++)
                #pragma unroll
                for (int q = 0; q < 4; q++) c[mi][f][q] = 0.f;

        #pragma unroll
        for (int kc = 0; kc < 2; kc++) {
            // ---- convert feats chunk -> A_hi + A_lo (single global read) ----
            __syncthreads();   // prior readers of A buffers done (and B staged)
            const float* src = kc ? g_agg : x;
            #pragma unroll
            for (int i = tid; i < 2048; i += 256) {     // 16B chunks
                int row = i >> 4, kk = (i & 15) * 8;
                const float* gp = src + (size_t)(r0 + row) * 128 + kk;
                float4 v0 = ((const float4*)gp)[0];
                float4 v1 = ((const float4*)gp)[1];
                uint32_t h0 = pk_hi(v0.x, v0.y), h1 = pk_hi(v0.z, v0.w);
                uint32_t h2 = pk_hi(v1.x, v1.y), h3 = pk_hi(v1.z, v1.w);
                uint32_t off = (uint32_t)row * K3_AROW + (uint32_t)kk * 2;
                sts128(sb + A_HI + off, h0, h1, h2, h3);
                sts128(sb + A_LO + off,
                       pk_lo_from(h0, v0.x, v0.y), pk_lo_from(h1, v0.z, v0.w),
                       pk_lo_from(h2, v1.x, v1.y), pk_lo_from(h3, v1.z, v1.w));
            }
            __syncthreads();

            // ---- fused 3-product kstep loop over this chunk ----
            #pragma unroll
            for (int ks = 0; ks < 8; ks++) {
                uint32_t ak = (uint32_t)ks * 32;
                uint32_t bk = (uint32_t)(kc * 8 + ks) * 32;
                uint32_t ah[2][4], al[2][4], bh[4][4], bl[4][4];
                ldsm4(ah[0], sb + A_HI + aoff[0] + ak);
                ldsm4(ah[1], sb + A_HI + aoff[1] + ak);
                ldsm4(al[0], sb + A_LO + aoff[0] + ak);
                ldsm4(al[1], sb + A_LO + aoff[1] + ak);
                #pragma unroll
                for (int j2 = 0; j2 < 4; j2++) {
                    uint32_t ro = boff + (uint32_t)j2 * (16 * K3_BROW) + bk;
                    ldsm4(bh[j2], sb + B_HI + ro);
                    ldsm4(bl[j2], sb + B_LO + ro);
                }
                #pragma unroll
                for (int mi = 0; mi < 2; mi++)
                    #pragma unroll
                    for (int f = 0; f < 8; f++) {
                        uint32_t bh0 = bh[f >> 1][(f & 1) * 2], bh1 = bh[f >> 1][(f & 1) * 2 + 1];
                        uint32_t bl0 = bl[f >> 1][(f & 1) * 2], bl1 = bl[f >> 1][(f & 1) * 2 + 1];
                        mma16816(c[mi][f], ah[mi], bh0, bh1);
                        mma16816(c[mi][f], ah[mi], bl0, bl1);
                        mma16816(c[mi][f], al[mi], bh0, bh1);
                    }
            }
        }

        // ---- epilogue: bias + relu + direct STG from fragments ----
        #pragma unroll
        for (int mi = 0; mi < 2; mi++) {
            int row = r0 + wm * 32 + mi * 16 + (lane >> 2);
            #pragma unroll
            for (int f = 0; f < 8; f++) {
                int col = wn * 64 + f * 8 + (lane & 3) * 2;
                float2 v0, v1;
                v0.x = fmaxf(c[mi][f][0] + bias[f].x, 0.f);
                v0.y = fmaxf(c[mi][f][1] + bias[f].y, 0.f);
                v1.x = fmaxf(c[mi][f][2] + bias[f].x, 0.f);
                v1.y = fmaxf(c[mi][f][3] + bias[f].y, 0.f);
                *(float2*)(out + (size_t)row * OUTF + col)       = v0;
                *(float2*)(out + (size_t)(row + 8) * OUTF + col) = v1;
            }
        }
    }
}

// ---------------------------------------------------------------------------
extern "C" void kernel_launch(void* const* d_in, const int* in_sizes, int n_in,
                              void* d_out, int out_size)
{
    const float* x     = (const float*)d_in[0];
    const float* W_s   = (const float*)d_in[1];
    const float* b_s   = (const float*)d_in[2];
    const float* W_h   = (const float*)d_in[3];
    const float* b_h   = (const float*)d_in[4];
    const float* W_out = (const float*)d_in[5];
    const float* b_out = (const float*)d_in[6];
    // d_in[7] = batch (int64) — equal-size sorted graphs; unused.
    float* out = (float*)d_out;

    int k1_smem = (INF_ * FLR + INF_ * SS + FLR + 8 + 8 * 8 * K1_RS) * (int)sizeof(float);
    cudaFuncSetAttribute(k1_embed, cudaFuncAttributeMaxDynamicSharedMemorySize, k1_smem);
    cudaFuncSetAttribute(k3_mma,   cudaFuncAttributeMaxDynamicSharedMemorySize, K3_SMEM);

    k0_convW<<<64, 256>>>(W_out);
    k1_embed<<<NN / 64, 256, k1_smem>>>(x, W_s, b_s, W_h, b_h);
    k2_knn_agg<<<NB * (LG / 8), 256>>>();
    k3_mma<<<148, 256, K3_SMEM>>>(x, b_out, out);
}